// round 1
// baseline (speedup 1.0000x reference)
#include <cuda_runtime.h>
#include <math_constants.h>

#define H 32
#define L 8192
#define D 128
#define ROWS (H * L)
#define GLOBAL_TOKENS 4

// ---- output layout (elements, fp32, concatenated in reference return order) ----
// kv (2,1,32,8192,128) | num_insertions (32) | pos_new (262144) | kq_new (33554432)
// | k_scales (262144) | k_zeros (262144) | vq_new (33554432) | v_scales (262144) | v_zeros (262144)
#define KV_K_OFF 0
#define KV_V_OFF 33554432
#define NI_OFF   67108864
#define POS_OFF  67108896
#define KQ_OFF   67371040
#define KS_OFF   100925472
#define KZ_OFF   101187616
#define VQ_OFF   101449760
#define VS_OFF   135004192
#define VZ_OFF   135266336

__device__ float g_scores[ROWS];
__device__ int   g_evict[H];

__global__ void __launch_bounds__(256) main_pass(
    const int4*  __restrict__ kq,  const int4*  __restrict__ vq,
    const float* __restrict__ ks,  const float* __restrict__ kz,
    const float* __restrict__ vs,  const float* __restrict__ vz,
    const int*   __restrict__ pos, const float4* __restrict__ w4,
    float* __restrict__ out)
{
    int warp = (blockIdx.x * 256 + threadIdx.x) >> 5;
    if (warp >= ROWS) return;
    int lane = threadIdx.x & 31;
    int row  = warp;              // row = h*L + l
    int h    = row >> 13;
    int l    = row & (L - 1);

    // 128-bit coalesced loads: 4 ints per lane per tensor
    int4 kqi = kq[(size_t)row * 32 + lane];
    int4 vqi = vq[(size_t)row * 32 + lane];
    float sk = ks[row], zk = kz[row];
    float sv = vs[row], zv = vz[row];
    float4 wv = w4[h * 32 + lane];

    // dequant (fma is monotone in q for s>0 => row min/max match reference)
    float k0 = fmaf((float)kqi.x, sk, zk);
    float k1 = fmaf((float)kqi.y, sk, zk);
    float k2 = fmaf((float)kqi.z, sk, zk);
    float k3 = fmaf((float)kqi.w, sk, zk);
    float v0 = fmaf((float)vqi.x, sv, zv);
    float v1 = fmaf((float)vqi.y, sv, zv);
    float v2 = fmaf((float)vqi.z, sv, zv);
    float v3 = fmaf((float)vqi.w, sv, zv);

    // per-lane partials
    float sc  = k0 * wv.x + k1 * wv.y + k2 * wv.z + k3 * wv.w;
    float kmn = fminf(fminf(k0, k1), fminf(k2, k3));
    float kmx = fmaxf(fmaxf(k0, k1), fmaxf(k2, k3));
    float vmn = fminf(fminf(v0, v1), fminf(v2, v3));
    float vmx = fmaxf(fmaxf(v0, v1), fmaxf(v2, v3));

    // warp-wide reductions
    #pragma unroll
    for (int o = 16; o; o >>= 1) {
        sc  +=       __shfl_xor_sync(0xffffffffu, sc,  o);
        kmn = fminf(kmn, __shfl_xor_sync(0xffffffffu, kmn, o));
        kmx = fmaxf(kmx, __shfl_xor_sync(0xffffffffu, kmx, o));
        vmn = fminf(vmn, __shfl_xor_sync(0xffffffffu, vmn, o));
        vmx = fmaxf(vmx, __shfl_xor_sync(0xffffffffu, vmx, o));
    }

    // write dequantized kv
    ((float4*)(out + KV_K_OFF))[(size_t)row * 32 + lane] = make_float4(k0, k1, k2, k3);
    ((float4*)(out + KV_V_OFF))[(size_t)row * 32 + lane] = make_float4(v0, v1, v2, v3);

    // requantize (scale via exact /15, per-row reciprocal for the elementwise divide)
    float ksn = fmaxf((kmx - kmn) / 15.0f, 1e-6f);
    float vsn = fmaxf((vmx - vmn) / 15.0f, 1e-6f);
    float kin = 1.0f / ksn;
    float vin = 1.0f / vsn;

    float q0 = fminf(fmaxf(rintf((k0 - kmn) * kin), 0.0f), 15.0f);
    float q1 = fminf(fmaxf(rintf((k1 - kmn) * kin), 0.0f), 15.0f);
    float q2 = fminf(fmaxf(rintf((k2 - kmn) * kin), 0.0f), 15.0f);
    float q3 = fminf(fmaxf(rintf((k3 - kmn) * kin), 0.0f), 15.0f);
    ((float4*)(out + KQ_OFF))[(size_t)row * 32 + lane] = make_float4(q0, q1, q2, q3);

    float p0 = fminf(fmaxf(rintf((v0 - vmn) * vin), 0.0f), 15.0f);
    float p1 = fminf(fmaxf(rintf((v1 - vmn) * vin), 0.0f), 15.0f);
    float p2 = fminf(fmaxf(rintf((v2 - vmn) * vin), 0.0f), 15.0f);
    float p3 = fminf(fmaxf(rintf((v3 - vmn) * vin), 0.0f), 15.0f);
    ((float4*)(out + VQ_OFF))[(size_t)row * 32 + lane] = make_float4(p0, p1, p2, p3);

    if (lane == 0) {
        int p = pos[row];
        out[POS_OFF + row] = (float)p;
        out[KS_OFF + row] = ksn;
        out[KZ_OFF + row] = kmn;
        out[VS_OFF + row] = vsn;
        out[VZ_OFF + row] = vmn;
        float s = sc;
        if (l < GLOBAL_TOKENS) s = CUDART_INF_F;     // protect global tokens
        if (p == -1)           s = -CUDART_INF_F;    // empty slots first (overrides)
        g_scores[row] = s;
    }
}

__global__ void __launch_bounds__(256) argmin_pass()
{
    int h = blockIdx.x;
    int tid = threadIdx.x;
    float best = CUDART_INF_F;
    int bidx = 0x7fffffff;
    for (int l = tid; l < L; l += 256) {
        float s = g_scores[h * L + l];
        if (s < best || (s == best && l < bidx)) { best = s; bidx = l; }
    }
    __shared__ float sb[256];
    __shared__ int   si[256];
    sb[tid] = best; si[tid] = bidx;
    __syncthreads();
    for (int o = 128; o; o >>= 1) {
        if (tid < o) {
            float s2 = sb[tid + o]; int i2 = si[tid + o];
            if (s2 < sb[tid] || (s2 == sb[tid] && i2 < si[tid])) { sb[tid] = s2; si[tid] = i2; }
        }
        __syncthreads();
    }
    if (tid == 0) g_evict[h] = si[0];
}

__global__ void __launch_bounds__(128) fixup(
    const float* __restrict__ k_val, const float* __restrict__ v_val,
    const int*   __restrict__ pos,   const int*   __restrict__ input_pos,
    float* __restrict__ out)
{
    int h = blockIdx.x;
    int d = threadIdx.x;        // 0..127
    int evict = g_evict[h];
    int row = h * L + evict;

    float kvl = k_val[h * D + d];
    float vvl = v_val[h * D + d];
    out[KV_K_OFF + (size_t)row * D + d] = kvl;
    out[KV_V_OFF + (size_t)row * D + d] = vvl;

    // block reduce min/max over 128 threads (4 warps)
    int lane = d & 31, wid = d >> 5;
    float kmn = kvl, kmx = kvl, vmn = vvl, vmx = vvl;
    #pragma unroll
    for (int o = 16; o; o >>= 1) {
        kmn = fminf(kmn, __shfl_xor_sync(0xffffffffu, kmn, o));
        kmx = fmaxf(kmx, __shfl_xor_sync(0xffffffffu, kmx, o));
        vmn = fminf(vmn, __shfl_xor_sync(0xffffffffu, vmn, o));
        vmx = fmaxf(vmx, __shfl_xor_sync(0xffffffffu, vmx, o));
    }
    __shared__ float red[4][4];
    if (lane == 0) { red[0][wid] = kmn; red[1][wid] = kmx; red[2][wid] = vmn; red[3][wid] = vmx; }
    __syncthreads();
    kmn = fminf(fminf(red[0][0], red[0][1]), fminf(red[0][2], red[0][3]));
    kmx = fmaxf(fmaxf(red[1][0], red[1][1]), fmaxf(red[1][2], red[1][3]));
    vmn = fminf(fminf(red[2][0], red[2][1]), fminf(red[2][2], red[2][3]));
    vmx = fmaxf(fmaxf(red[3][0], red[3][1]), fmaxf(red[3][2], red[3][3]));

    float ksn = fmaxf((kmx - kmn) / 15.0f, 1e-6f);
    float vsn = fmaxf((vmx - vmn) / 15.0f, 1e-6f);
    float kin = 1.0f / ksn;
    float vin = 1.0f / vsn;

    out[KQ_OFF + (size_t)row * D + d] = fminf(fmaxf(rintf((kvl - kmn) * kin), 0.0f), 15.0f);
    out[VQ_OFF + (size_t)row * D + d] = fminf(fmaxf(rintf((vvl - vmn) * vin), 0.0f), 15.0f);

    if (d == 0) {
        out[KS_OFF + row] = ksn;
        out[KZ_OFF + row] = kmn;
        out[VS_OFF + row] = vsn;
        out[VZ_OFF + row] = vmn;
        out[POS_OFF + row] = (float)input_pos[0];
        out[NI_OFF + h] = (pos[row] == -1) ? 1.0f : 0.0f;
    }
}

extern "C" void kernel_launch(void* const* d_in, const int* in_sizes, int n_in,
                              void* d_out, int out_size)
{
    const int4*   kq        = (const int4*)d_in[0];
    const int4*   vq        = (const int4*)d_in[1];
    const float*  ks        = (const float*)d_in[2];
    const float*  kz        = (const float*)d_in[3];
    const float*  vs        = (const float*)d_in[4];
    const float*  vz        = (const float*)d_in[5];
    const int*    pos       = (const int*)d_in[6];
    const int*    input_pos = (const int*)d_in[7];
    const float*  k_val     = (const float*)d_in[8];
    const float*  v_val     = (const float*)d_in[9];
    const float4* w4        = (const float4*)d_in[10];
    float* out = (float*)d_out;

    main_pass<<<ROWS / 8, 256>>>(kq, vq, ks, kz, vs, vz, pos, w4, out);
    argmin_pass<<<H, 256>>>();
    fixup<<<H, D>>>(k_val, v_val, pos, input_pos, out);
}

// round 2
// speedup vs baseline: 1.0415x; 1.0415x over previous
#include <cuda_runtime.h>
#include <math_constants.h>

#define H 32
#define L 8192
#define D 128
#define ROWS (H * L)
#define GLOBAL_TOKENS 4

// ---- output layout (elements, fp32, concatenated in reference return order) ----
#define KV_K_OFF 0
#define KV_V_OFF 33554432
#define NI_OFF   67108864
#define POS_OFF  67108896
#define KQ_OFF   67371040
#define KS_OFF   100925472
#define KZ_OFF   101187616
#define VQ_OFF   101449760
#define VS_OFF   135004192
#define VZ_OFF   135266336

// packed argmin keys: (ordered_uint(score) << 32) | slot_index ; min over key = argmin
__device__ unsigned long long g_evict_key[H];

__device__ __forceinline__ unsigned int float_to_ordered(float f) {
    unsigned int b = __float_as_uint(f);
    return (b & 0x80000000u) ? ~b : (b | 0x80000000u);
}

__global__ void __launch_bounds__(256) main_pass(
    const int4*  __restrict__ kq,  const int4*  __restrict__ vq,
    const float* __restrict__ ks,  const float* __restrict__ kz,
    const float* __restrict__ vs,  const float* __restrict__ vz,
    const int*   __restrict__ pos, const float4* __restrict__ w4,
    float* __restrict__ out)
{
    int warp = (blockIdx.x * 256 + threadIdx.x) >> 5;   // row index, grid exact
    int lane = threadIdx.x & 31;
    int row  = warp;              // row = h*L + l
    int h    = row >> 13;
    int l    = row & (L - 1);

    // 128-bit coalesced streaming loads
    int4 kqi = __ldcs(&kq[(size_t)row * 32 + lane]);
    int4 vqi = __ldcs(&vq[(size_t)row * 32 + lane]);
    float sk = ks[row], zk = kz[row];
    float sv = vs[row], zv = vz[row];
    float4 wv = w4[h * 32 + lane];

    // integer min/max per lane, then single-instruction warp REDUX
    int kq_mn = min(min(kqi.x, kqi.y), min(kqi.z, kqi.w));
    int kq_mx = max(max(kqi.x, kqi.y), max(kqi.z, kqi.w));
    int vq_mn = min(min(vqi.x, vqi.y), min(vqi.z, vqi.w));
    int vq_mx = max(max(vqi.x, vqi.y), max(vqi.z, vqi.w));
    kq_mn = __reduce_min_sync(0xffffffffu, kq_mn);
    kq_mx = __reduce_max_sync(0xffffffffu, kq_mx);
    vq_mn = __reduce_min_sync(0xffffffffu, vq_mn);
    vq_mx = __reduce_max_sync(0xffffffffu, vq_mx);

    // dequant (fma monotone in q for s>=0 => fmaf(qmin)=row min of dequant values)
    float k0 = fmaf((float)kqi.x, sk, zk);
    float k1 = fmaf((float)kqi.y, sk, zk);
    float k2 = fmaf((float)kqi.z, sk, zk);
    float k3 = fmaf((float)kqi.w, sk, zk);
    float v0 = fmaf((float)vqi.x, sv, zv);
    float v1 = fmaf((float)vqi.y, sv, zv);
    float v2 = fmaf((float)vqi.z, sv, zv);
    float v3 = fmaf((float)vqi.w, sv, zv);

    float kmn = fmaf((float)kq_mn, sk, zk);
    float kmx = fmaf((float)kq_mx, sk, zk);
    float vmn = fmaf((float)vq_mn, sv, zv);
    float vmx = fmaf((float)vq_mx, sv, zv);

    // score dot-product (warp sum)
    float sc = k0 * wv.x + k1 * wv.y + k2 * wv.z + k3 * wv.w;
    #pragma unroll
    for (int o = 16; o; o >>= 1)
        sc += __shfl_xor_sync(0xffffffffu, sc, o);

    // write dequantized kv (streaming)
    __stcs(&((float4*)(out + KV_K_OFF))[(size_t)row * 32 + lane], make_float4(k0, k1, k2, k3));
    __stcs(&((float4*)(out + KV_V_OFF))[(size_t)row * 32 + lane], make_float4(v0, v1, v2, v3));

    // requantize
    float ksn = fmaxf((kmx - kmn) / 15.0f, 1e-6f);
    float vsn = fmaxf((vmx - vmn) / 15.0f, 1e-6f);
    float kin = 1.0f / ksn;
    float vin = 1.0f / vsn;

    float q0 = fminf(fmaxf(rintf((k0 - kmn) * kin), 0.0f), 15.0f);
    float q1 = fminf(fmaxf(rintf((k1 - kmn) * kin), 0.0f), 15.0f);
    float q2 = fminf(fmaxf(rintf((k2 - kmn) * kin), 0.0f), 15.0f);
    float q3 = fminf(fmaxf(rintf((k3 - kmn) * kin), 0.0f), 15.0f);
    __stcs(&((float4*)(out + KQ_OFF))[(size_t)row * 32 + lane], make_float4(q0, q1, q2, q3));

    float p0 = fminf(fmaxf(rintf((v0 - vmn) * vin), 0.0f), 15.0f);
    float p1 = fminf(fmaxf(rintf((v1 - vmn) * vin), 0.0f), 15.0f);
    float p2 = fminf(fmaxf(rintf((v2 - vmn) * vin), 0.0f), 15.0f);
    float p3 = fminf(fmaxf(rintf((v3 - vmn) * vin), 0.0f), 15.0f);
    __stcs(&((float4*)(out + VQ_OFF))[(size_t)row * 32 + lane], make_float4(p0, p1, p2, p3));

    __shared__ unsigned long long skey[8];
    if (lane == 0) {
        int p = pos[row];
        out[POS_OFF + row] = (float)p;
        out[KS_OFF + row] = ksn;
        out[KZ_OFF + row] = kmn;
        out[VS_OFF + row] = vsn;
        out[VZ_OFF + row] = vmn;
        float s = sc;
        if (l < GLOBAL_TOKENS) s = CUDART_INF_F;     // protect global tokens
        if (p == -1)           s = -CUDART_INF_F;    // empty slots first (overrides)
        skey[threadIdx.x >> 5] = ((unsigned long long)float_to_ordered(s) << 32) | (unsigned int)l;
    }
    __syncthreads();
    if (threadIdx.x == 0) {
        unsigned long long best = skey[0];
        #pragma unroll
        for (int i = 1; i < 8; i++) best = min(best, skey[i]);
        atomicMin(&g_evict_key[blockIdx.x >> 10], best);   // 1024 blocks per head
    }
}

__global__ void __launch_bounds__(128) fixup(
    const float* __restrict__ k_val, const float* __restrict__ v_val,
    const int*   __restrict__ pos,   const int*   __restrict__ input_pos,
    float* __restrict__ out)
{
    int h = blockIdx.x;
    int d = threadIdx.x;        // 0..127
    int evict = (int)(unsigned int)(g_evict_key[h] & 0xffffffffu);
    int row = h * L + evict;

    float kvl = k_val[h * D + d];
    float vvl = v_val[h * D + d];
    out[KV_K_OFF + (size_t)row * D + d] = kvl;
    out[KV_V_OFF + (size_t)row * D + d] = vvl;

    // block reduce min/max over 128 threads (4 warps)
    int lane = d & 31, wid = d >> 5;
    float kmn = kvl, kmx = kvl, vmn = vvl, vmx = vvl;
    #pragma unroll
    for (int o = 16; o; o >>= 1) {
        kmn = fminf(kmn, __shfl_xor_sync(0xffffffffu, kmn, o));
        kmx = fmaxf(kmx, __shfl_xor_sync(0xffffffffu, kmx, o));
        vmn = fminf(vmn, __shfl_xor_sync(0xffffffffu, vmn, o));
        vmx = fmaxf(vmx, __shfl_xor_sync(0xffffffffu, vmx, o));
    }
    __shared__ float red[4][4];
    if (lane == 0) { red[0][wid] = kmn; red[1][wid] = kmx; red[2][wid] = vmn; red[3][wid] = vmx; }
    __syncthreads();
    kmn = fminf(fminf(red[0][0], red[0][1]), fminf(red[0][2], red[0][3]));
    kmx = fmaxf(fmaxf(red[1][0], red[1][1]), fmaxf(red[1][2], red[1][3]));
    vmn = fminf(fminf(red[2][0], red[2][1]), fminf(red[2][2], red[2][3]));
    vmx = fmaxf(fmaxf(red[3][0], red[3][1]), fmaxf(red[3][2], red[3][3]));

    float ksn = fmaxf((kmx - kmn) / 15.0f, 1e-6f);
    float vsn = fmaxf((vmx - vmn) / 15.0f, 1e-6f);
    float kin = 1.0f / ksn;
    float vin = 1.0f / vsn;

    out[KQ_OFF + (size_t)row * D + d] = fminf(fmaxf(rintf((kvl - kmn) * kin), 0.0f), 15.0f);
    out[VQ_OFF + (size_t)row * D + d] = fminf(fmaxf(rintf((vvl - vmn) * vin), 0.0f), 15.0f);

    if (d == 0) {
        out[KS_OFF + row] = ksn;
        out[KZ_OFF + row] = kmn;
        out[VS_OFF + row] = vsn;
        out[VZ_OFF + row] = vmn;
        out[POS_OFF + row] = (float)input_pos[0];
        out[NI_OFF + h] = (pos[row] == -1) ? 1.0f : 0.0f;
    }
}

extern "C" void kernel_launch(void* const* d_in, const int* in_sizes, int n_in,
                              void* d_out, int out_size)
{
    const int4*   kq        = (const int4*)d_in[0];
    const int4*   vq        = (const int4*)d_in[1];
    const float*  ks        = (const float*)d_in[2];
    const float*  kz        = (const float*)d_in[3];
    const float*  vs        = (const float*)d_in[4];
    const float*  vz        = (const float*)d_in[5];
    const int*    pos       = (const int*)d_in[6];
    const int*    input_pos = (const int*)d_in[7];
    const float*  k_val     = (const float*)d_in[8];
    const float*  v_val     = (const float*)d_in[9];
    const float4* w4        = (const float4*)d_in[10];
    float* out = (float*)d_out;

    // reset argmin keys to +inf (0xFF.. bytes = max u64) — graph-capturable memset node
    void* keys_ptr = nullptr;
    cudaGetSymbolAddress(&keys_ptr, g_evict_key);
    cudaMemsetAsync(keys_ptr, 0xFF, H * sizeof(unsigned long long));

    main_pass<<<ROWS / 8, 256>>>(kq, vq, ks, kz, vs, vz, pos, w4, out);
    fixup<<<H, D>>>(k_val, v_val, pos, input_pos, out);
}